// round 8
// baseline (speedup 1.0000x reference)
#include <cuda_runtime.h>
#include <cuda_fp16.h>
#include <cstdint>

// Problem constants
#define N_NODES 100000
#define N_EDGES 400000
#define DIM     128
#define KDIM    384       // 3*DIM
#define HID     768       // 6*DIM
#define TILE_M  128
#define N_TILES (N_EDGES / TILE_M)   // 3125
#define N_ITERS 12                   // 768 / 64 n-cols per iter
#define KTILES  24                   // 384 / 16

// W1 in fp16, pre-laid-out in m16n8k16 B-fragment order:
// [iter 12][ntile 8][ktile 24][lane 32][2 x b32]  (48 KB per iter)
__device__ __align__(16) __half g_w1frag[HID * KDIM];

static constexpr uint32_t B_ITER_BYTES = 8 * KTILES * 32 * 8;  // 49152

// ---------------- SMEM layout ----------------
// A (feat fragments): [mtile 8][ktile 24][lane 32][4 x b32] = 98304
static constexpr int SM_A    = 0;
static constexpr int SM_B    = 98304;    // 2 x 49152 double buffer
static constexpr int SM_W2   = 196608;   // 768 f32
static constexpr int SM_B1   = 199680;   // 768 f32
static constexpr int SM_PART = 202752;   // 2 x 128 f32
static constexpr int SMEM_TOTAL = 203776;

// ---------------- helpers ----------------
__device__ __forceinline__ uint32_t smem_u32(const void* p) {
    uint32_t a;
    asm("{ .reg .u64 t; cvta.to.shared.u64 t, %1; cvt.u32.u64 %0, t; }" : "=r"(a) : "l"(p));
    return a;
}
__device__ __forceinline__ void cp16(uint32_t dst, const void* src) {
    asm volatile("cp.async.cg.shared.global [%0], [%1], 16;" :: "r"(dst), "l"(src) : "memory");
}
__device__ __forceinline__ void cp_commit() {
    asm volatile("cp.async.commit_group;" ::: "memory");
}
template <int N>
__device__ __forceinline__ void cp_wait() {
    asm volatile("cp.async.wait_group %0;" :: "n"(N) : "memory");
}
__device__ __forceinline__ void mma16816(float* d, const uint32_t* a, const uint32_t* b) {
    asm volatile(
        "mma.sync.aligned.m16n8k16.row.col.f32.f16.f16.f32 "
        "{%0,%1,%2,%3}, {%4,%5,%6,%7}, {%8,%9}, {%0,%1,%2,%3};"
        : "+f"(d[0]), "+f"(d[1]), "+f"(d[2]), "+f"(d[3])
        : "r"(a[0]), "r"(a[1]), "r"(a[2]), "r"(a[3]), "r"(b[0]), "r"(b[1]));
}

// A-fragment smem byte offset for (row r in 0..127, kpair p in 0..191)
// m16n8k16 A layout: reg w = (row>=8) + 2*(kpair>=4); lane = (r&7)*4 + (p&3)
__device__ __forceinline__ uint32_t a_frag_off(int r, int p) {
    int kt   = p >> 3;
    int kp   = p & 7;
    int ln   = ((r & 7) << 2) + (kp & 3);
    int word = ((r >> 3) & 1) + ((kp >> 2) << 1);
    int mt   = r >> 4;
    return (uint32_t)(((mt * KTILES + kt) << 9) + (ln << 4) + (word << 2));
}

// ---------------- prep: W1 fp32 -> fp16 fragment-ordered ----------------
__global__ void prep_w1_kernel(const float* __restrict__ W1) {
    int i = blockIdx.x * blockDim.x + threadIdx.x;
    if (i >= HID * KDIM) return;
    int n = i / KDIM;
    int k = i - n * KDIM;
    int iter = n >> 6;
    int np   = n & 63;
    int nt   = np >> 3;
    int g    = np & 7;
    int kt   = k >> 4;
    int kk   = k & 15;
    int w    = kk >> 3;          // b-frag word (k<8 vs k>=8)
    int t    = (kk & 7) >> 1;
    int half = kk & 1;
    uint32_t off = (uint32_t)iter * B_ITER_BYTES
                 + (uint32_t)((nt * KTILES + kt) << 8)
                 + (uint32_t)(((g << 2) + t) << 3) + (uint32_t)(w << 2) + (uint32_t)(half << 1);
    *(__half*)((char*)g_w1frag + off) = __float2half_rn(W1[i]);
}

// ---------------- main fused kernel ----------------
__global__ void __launch_bounds__(256, 1) edge_mlp_hmma(
    const float* __restrict__ x,
    const int* __restrict__ ei,     // int32 (JAX x64 disabled: int64 request -> int32 array)
    const float* __restrict__ b1g,
    const float* __restrict__ w2g,
    const float* __restrict__ b2g,
    float* __restrict__ out)
{
    extern __shared__ char smem[];
    const uint32_t sb = smem_u32(smem);
    const int tid  = threadIdx.x;
    const int lane = tid & 31;
    const int wid  = tid >> 5;
    const int mg   = wid & 3;      // 4 m-groups (32 rows each)
    const int ng   = wid >> 2;     // 2 n-groups (32 cols per iter each)
    const int e0   = blockIdx.x * TILE_M;

    // Kick off cp.async for B iters 0 and 1 (one commit group per iter)
    {
        const char* gsrc = (const char*)g_w1frag;
#pragma unroll
        for (int it = 0; it < 2; it++) {
            uint32_t d = sb + SM_B + it * B_ITER_BYTES;
            const char* s = gsrc + it * B_ITER_BYTES;
#pragma unroll
            for (int j = 0; j < 12; j++)
                cp16(d + tid * 16 + j * 4096, s + tid * 16 + j * 4096);
            cp_commit();
        }
    }

    // Stage w2 / b1 into smem
    float* w2s = (float*)(smem + SM_W2);
    float* b1s = (float*)(smem + SM_B1);
#pragma unroll
    for (int i = 0; i < 3; i++) { w2s[tid + i * 256] = w2g[tid + i * 256];
                                  b1s[tid + i * 256] = b1g[tid + i * 256]; }

    // ---- build feat tile into smem A-fragment layout ----
    // 256 threads: thread handles row r = tid&127, j-quarter (tid>>7)*16..+15
    // Sections by KPAIR base: mean -> 0, prod -> 64, sqdiff -> 128.
    {
        const int r  = tid & 127;
        const int qb = (tid >> 7) * 16;
        const int i0 = ei[e0 + r];
        const int i1 = ei[N_EDGES + e0 + r];
        const float4* p0 = (const float4*)x + (size_t)i0 * 32 + qb;
        const float4* p1 = (const float4*)x + (size_t)i1 * 32 + qb;
        char* As = smem + SM_A;
#pragma unroll 4
        for (int q = 0; q < 16; q++) {
            float4 a = p0[q];
            float4 c = p1[q];
            int qg = qb + q;
            __half2 h;
            // mean (kpairs 2qg, 2qg+1)
            h = __floats2half2_rn((a.x + c.x) * 0.5f, (a.y + c.y) * 0.5f);
            *(uint32_t*)(As + a_frag_off(r, 2 * qg))          = *(uint32_t*)&h;
            h = __floats2half2_rn((a.z + c.z) * 0.5f, (a.w + c.w) * 0.5f);
            *(uint32_t*)(As + a_frag_off(r, 2 * qg + 1))      = *(uint32_t*)&h;
            // prod (kpairs 64+2qg, 64+2qg+1)
            h = __floats2half2_rn(a.x * c.x, a.y * c.y);
            *(uint32_t*)(As + a_frag_off(r, 64 + 2 * qg))     = *(uint32_t*)&h;
            h = __floats2half2_rn(a.z * c.z, a.w * c.w);
            *(uint32_t*)(As + a_frag_off(r, 64 + 2 * qg + 1)) = *(uint32_t*)&h;
            // sqdiff (kpairs 128+2qg, 128+2qg+1)
            float d0 = a.x - c.x, d1 = a.y - c.y, d2 = a.z - c.z, d3 = a.w - c.w;
            h = __floats2half2_rn(d0 * d0, d1 * d1);
            *(uint32_t*)(As + a_frag_off(r, 128 + 2 * qg))     = *(uint32_t*)&h;
            h = __floats2half2_rn(d2 * d2, d3 * d3);
            *(uint32_t*)(As + a_frag_off(r, 128 + 2 * qg + 1)) = *(uint32_t*)&h;
        }
    }

    // 4 per-lane row accumulators: [mt0 row g, mt0 row g+8, mt1 row g, mt1 row g+8]
    float accv[4] = {0.f, 0.f, 0.f, 0.f};
    const int t4 = lane & 3;

    const uint32_t a_off0 = (uint32_t)SM_A + (uint32_t)(mg * 2 * KTILES) * 512u + (uint32_t)lane * 16u;

#pragma unroll 1
    for (int it = 0; it < N_ITERS; it++) {
        cp_wait<1>();
        __syncthreads();   // buf[it&1] ready; also orders feat writes on it==0

        const uint32_t b_off0 = (uint32_t)SM_B + (uint32_t)(it & 1) * B_ITER_BYTES
                              + (uint32_t)(ng * 4 * KTILES) * 256u + (uint32_t)lane * 8u;

        float C[8][4];
#pragma unroll
        for (int f = 0; f < 8; f++)
#pragma unroll
            for (int v = 0; v < 4; v++) C[f][v] = 0.f;

#pragma unroll
        for (int kt = 0; kt < KTILES; kt++) {
            uint4 A0 = *(const uint4*)(smem + a_off0 + (uint32_t)kt * 512u);
            uint4 A1 = *(const uint4*)(smem + a_off0 + (uint32_t)(KTILES * 512) + (uint32_t)kt * 512u);
            uint2 B0 = *(const uint2*)(smem + b_off0 + (uint32_t)(0 * KTILES + kt) * 256u);
            uint2 B1 = *(const uint2*)(smem + b_off0 + (uint32_t)(1 * KTILES + kt) * 256u);
            uint2 B2 = *(const uint2*)(smem + b_off0 + (uint32_t)(2 * KTILES + kt) * 256u);
            uint2 B3 = *(const uint2*)(smem + b_off0 + (uint32_t)(3 * KTILES + kt) * 256u);
            mma16816(C[0], (const uint32_t*)&A0, (const uint32_t*)&B0);
            mma16816(C[1], (const uint32_t*)&A0, (const uint32_t*)&B1);
            mma16816(C[2], (const uint32_t*)&A0, (const uint32_t*)&B2);
            mma16816(C[3], (const uint32_t*)&A0, (const uint32_t*)&B3);
            mma16816(C[4], (const uint32_t*)&A1, (const uint32_t*)&B0);
            mma16816(C[5], (const uint32_t*)&A1, (const uint32_t*)&B1);
            mma16816(C[6], (const uint32_t*)&A1, (const uint32_t*)&B2);
            mma16816(C[7], (const uint32_t*)&A1, (const uint32_t*)&B3);
        }

        // fold relu(. + b1) * w2 into per-row accumulators
        const int nb = it * 64 + ng * 32 + t4 * 2;
#pragma unroll
        for (int nt = 0; nt < 4; nt++) {
            const int c0 = nb + nt * 8;
            float2 bb = *(const float2*)&b1s[c0];
            float2 ww = *(const float2*)&w2s[c0];
#pragma unroll
            for (int mt = 0; mt < 2; mt++) {
                float* d = C[mt * 4 + nt];
                accv[mt * 2 + 0] += fmaxf(d[0] + bb.x, 0.f) * ww.x
                                 + fmaxf(d[1] + bb.y, 0.f) * ww.y;
                accv[mt * 2 + 1] += fmaxf(d[2] + bb.x, 0.f) * ww.x
                                 + fmaxf(d[3] + bb.y, 0.f) * ww.y;
            }
        }

        __syncthreads();   // everyone done reading buf[it&1]
        if (it + 2 < N_ITERS) {
            uint32_t d = sb + SM_B + (uint32_t)(it & 1) * B_ITER_BYTES;
            const char* s = (const char*)g_w1frag + (size_t)(it + 2) * B_ITER_BYTES;
#pragma unroll
            for (int j = 0; j < 12; j++)
                cp16(d + tid * 16 + j * 4096, s + tid * 16 + j * 4096);
        }
        cp_commit();  // always commit (possibly empty) to keep wait_group<1> bookkeeping uniform
    }

    // reduce the 4 lanes sharing a g-group (xor over t bits)
#pragma unroll
    for (int i = 0; i < 4; i++) {
        accv[i] += __shfl_xor_sync(0xffffffffu, accv[i], 1);
        accv[i] += __shfl_xor_sync(0xffffffffu, accv[i], 2);
    }

    float* part = (float*)(smem + SM_PART);
    if (t4 == 0) {
        const int g = lane >> 2;
        const int rb = mg * 32;
        part[ng * 128 + rb + g]      = accv[0];
        part[ng * 128 + rb + 8 + g]  = accv[1];
        part[ng * 128 + rb + 16 + g] = accv[2];
        part[ng * 128 + rb + 24 + g] = accv[3];
    }
    __syncthreads();
    if (tid < 128)
        out[e0 + tid] = part[tid] + part[128 + tid] + b2g[0];
}

// ---------------- launch ----------------
extern "C" void kernel_launch(void* const* d_in, const int* in_sizes, int n_in,
                              void* d_out, int out_size) {
    const float* x  = (const float*)d_in[0];
    const int*   ei = (const int*)d_in[1];   // int32 (JAX default: x64 disabled)
    // d_in[2] edge_attr3, d_in[3] edge_attr4, d_in[4] batch: unused by reference
    const float* W1 = (const float*)d_in[5];
    const float* b1 = (const float*)d_in[6];
    const float* W2 = (const float*)d_in[7];
    const float* b2 = (const float*)d_in[8];
    float* out = (float*)d_out;

    prep_w1_kernel<<<(HID * KDIM + 255) / 256, 256>>>(W1);

    cudaFuncSetAttribute(edge_mlp_hmma,
                         cudaFuncAttributeMaxDynamicSharedMemorySize, SMEM_TOTAL);
    edge_mlp_hmma<<<N_TILES, 256, SMEM_TOTAL>>>(x, ei, b1, W2, b2, out);
}